// round 15
// baseline (speedup 1.0000x reference)
#include <cuda_runtime.h>

#define HW   16384      // 128*128
#define NPIX 32768      // B * HW
#define NCLS 35

#define RBLK 128        // routing blocks (256 px each)
#define TBLK 256        // transpose blocks (128 px each)

// -------- device scratch (no allocs allowed) --------
__device__ int   d_cnt[NCLS];              // zero-init at load; re-zeroed by kC
__device__ int   d_clist[NCLS * NPIX];     // 4.6 MB
__device__ float d_xt[NPIX * 64];          // x' pixel-major, 8.4 MB
__device__ float d_ysc[NPIX * 64];         // y  pixel-major, 8.4 MB
__device__ float d_sum[128];
__device__ float d_sq[128];

// -------- packed f32x2 helpers (Blackwell FFMA2 — only via PTX) --------
__device__ __forceinline__ unsigned long long ffma2(unsigned long long a,
                                                    unsigned long long b,
                                                    unsigned long long c) {
    unsigned long long d;
    asm("fma.rn.f32x2 %0, %1, %2, %3;" : "=l"(d) : "l"(a), "l"(b), "l"(c));
    return d;
}
__device__ __forceinline__ unsigned long long addf2(unsigned long long a,
                                                    unsigned long long b) {
    unsigned long long d;
    asm("add.rn.f32x2 %0, %1, %2;" : "=l"(d) : "l"(a), "l"(b));
    return d;
}
__device__ __forceinline__ unsigned long long bcast2(float x) {
    unsigned long long d;
    unsigned xi = __float_as_uint(x);
    asm("mov.b64 %0, {%1, %1};" : "=l"(d) : "r"(xi));
    return d;
}
__device__ __forceinline__ float2 unpk(unsigned long long v) {
    float lo, hi;
    asm("mov.b64 {%0, %1}, %2;" : "=f"(lo), "=f"(hi) : "l"(v));
    return make_float2(lo, hi);
}

// -------- kA: role-split; routing staged through smem ------------------------
__global__ void __launch_bounds__(256, 3)
kA(const float* __restrict__ x, const float* __restrict__ layout,
   const float* __restrict__ pr, const float* __restrict__ conv_w,
   const float* __restrict__ conv_b, const float* __restrict__ pl) {
    __shared__ float shbuf[NCLS * 256];   // 35.8KB; routing stage / transpose tile
    int t   = threadIdx.x;
    int bid = blockIdx.x;

    if (bid < RBLK) {
        // ===== routing: 256 px/block; smem-staged argmax (structural MLP) ===
        if (bid == 0 && t < 128) { d_sum[t] = 0.f; d_sq[t] = 0.f; }
        int p0 = bid * 256;
        int b  = p0 >> 14;
        int hw0 = p0 & (HW - 1);
        const float* lb = layout + (size_t)b * NCLS * HW + hw0;

        // bulk copy layout[b, 0:35, hw0:hw0+256] -> smem (2240 indep LDG.128)
        #pragma unroll
        for (int it = 0; it < 9; it++) {
            int idx = it * 256 + t;
            if (idx < NCLS * 64) {
                int row = idx >> 6;          // class
                int col = idx & 63;          // float4 within 256 px
                float4 v = *(const float4*)(lb + (size_t)row * HW + col * 4);
                *(float4*)&shbuf[row * 256 + col * 4] = v;
            }
        }
        __syncthreads();

        // per-pixel argmax over 35 conflict-free LDS (first-max tie rule)
        float best = shbuf[t];
        int arg = 0;
        #pragma unroll
        for (int k = 1; k < NCLS; k++) {
            float v = shbuf[k * 256 + t];
            if (v > best) { best = v; arg = k; }
        }
        int slot = atomicAdd(&d_cnt[arg], 1);
        d_clist[arg * NPIX + slot] = p0 + t;
        return;
    }

    // ===== transpose: 128 px/block, x' = x + s, pixel-major out ==============
    float* tile = shbuf;                 // 128*65 = 8320 floats
    float* ssm  = shbuf + 8320;          // 128 floats
    int p0  = (bid - RBLK) * 128;
    int b   = p0 >> 14;
    int hw0 = p0 & (HW - 1);

    // threads 0..127: pos-scalar s (LUT trig)
    if (t < 128) {
        int hw = hw0 + t;
        int i  = hw >> 7;
        int j  = hw & 127;
        int jm = j % 3, im = i % 3;
        float xc  = (jm == 0) ? 1.0f : -0.5f;
        float xsn = (jm == 0) ? 0.0f : ((jm == 1) ? 0.8660254f : -0.8660254f);
        float yc  = (im == 0) ? 1.0f : -0.5f;
        float ysn = (im == 0) ? 0.0f : ((im == 1) ? 0.8660254f : -0.8660254f);
        float px = (float)i * (2.0f / 128.0f) - 1.0f;
        float py = (float)j * (2.0f / 128.0f) - 1.0f;
        float pl0 = pl[hw], pl1 = pl[HW + hw];
        const float* prb = pr + b * 2 * HW;
        float pr0 = prb[hw], pr1 = prb[HW + hw];
        float s = px * conv_w[0] + py * conv_w[1] + pl0 * conv_w[2]
                + pl1 * conv_w[3] + pr0 * conv_w[4] + pr1 * conv_w[5]
                + xc * conv_w[6] + xsn * conv_w[7]
                + yc * conv_w[8] + ysn * conv_w[9] + conv_b[0];
        ssm[t] = s;
    }

    // all 256 threads: 8 independent LDG.128 over pixels (128B in flight)
    {
        int px4 = t & 15;                  // float4 group within 64-px half
        int chb = t >> 4;                  // channel 0..15
        const float* xbase = x + (size_t)b * 64 * HW + hw0;
        float4 vv[8];
        #pragma unroll
        for (int r = 0; r < 8; r++) {
            int ch  = chb + (r & 3) * 16;
            int pxh = (r >> 2) * 64;
            vv[r] = *(const float4*)(xbase + (size_t)ch * HW + pxh + px4 * 4);
        }
        #pragma unroll
        for (int r = 0; r < 8; r++) {
            int ch  = chb + (r & 3) * 16;
            int pxb = (r >> 2) * 64 + px4 * 4;
            tile[(pxb + 0) * 65 + ch] = vv[r].x;
            tile[(pxb + 1) * 65 + ch] = vv[r].y;
            tile[(pxb + 2) * 65 + ch] = vv[r].z;
            tile[(pxb + 3) * 65 + ch] = vv[r].w;
        }
    }
    __syncthreads();

    // write pixel-major float4 rows, fusing +s (8 x 256 float4 = 128px x 64ch)
    #pragma unroll
    for (int r = 0; r < 8; r++) {
        int lin = r * 256 + t;
        int pp  = lin >> 4;
        int c4  = (lin & 15) << 2;
        float s = ssm[pp];
        float4 v;
        v.x = tile[pp * 65 + c4 + 0] + s;
        v.y = tile[pp * 65 + c4 + 1] + s;
        v.z = tile[pp * 65 + c4 + 2] + s;
        v.w = tile[pp * 65 + c4 + 3] + s;
        *(float4*)&d_xt[(size_t)(p0 + pp) * 64 + c4] = v;
    }
}

// -------- kB: grouped GEMM + in-block prefix scan ----------------------------
__global__ void __launch_bounds__(256, 2)
kB(const float* __restrict__ Wt, const float* __restrict__ bt) {
    __shared__ float Wsm[64 * 64];     // 16KB; aliased as reduction buf after GEMM
    __shared__ float xs[128 * 64];     // 32KB; aliased as scan buf before gather

    int t   = threadIdx.x;
    int bid = blockIdx.x;

    // ---- per-block prefix scan of per-class 128-px chunk counts (warp 0) ----
    int* sc = (int*)xs;                // sc[35] inclusive prefix
    if (t < 32) {
        unsigned m = 0xffffffffu;
        int a = (t < NCLS) ? ((d_cnt[t] + 127) >> 7) : 0;
        int bch = (t < NCLS - 32) ? ((d_cnt[32 + t] + 127) >> 7) : 0;
        #pragma unroll
        for (int off = 1; off < 32; off <<= 1) {
            int u = __shfl_up_sync(m, a, off);
            if (t >= off) a += u;
        }
        #pragma unroll
        for (int off = 1; off < 4; off <<= 1) {
            int u = __shfl_up_sync(m, bch, off);
            if (t >= off) bch += u;
        }
        int totalA = __shfl_sync(m, a, 31);
        sc[t] = a;
        if (t < 3) sc[32 + t] = totalA + bch;
    }
    __syncthreads();

    int total = sc[NCLS - 1];
    if (bid >= total) return;          // uniform exit

    // smallest k with sc[k] > bid
    int lo = 0, hi = NCLS;
    #pragma unroll
    for (int it = 0; it < 6; it++) {
        int mid = (lo + hi) >> 1;
        if (mid < NCLS && sc[mid] <= bid) lo = mid + 1; else hi = mid;
    }
    int k      = lo;
    int pfx    = (k > 0) ? sc[k - 1] : 0;
    int base   = (bid - pfx) << 7;
    int n      = min(128, d_cnt[k] - base);
    const int* clist = d_clist + k * NPIX + base;
    __syncthreads();                   // everyone done reading sc before xs reuse

    // load expert matrix (16KB)
    const float4* Wk4  = (const float4*)(Wt + (size_t)k * 4096);
    float4*       Wsm4 = (float4*)Wsm;
    #pragma unroll
    for (int r = 0; r < 4; r++) Wsm4[r * 256 + t] = Wk4[r * 256 + t];

    // gather x' rows, xor-swizzled by pixel (key = (pix>>2)&3)
    float4* xs4 = (float4*)xs;
    #pragma unroll
    for (int r = 0; r < 8; r++) {
        int lin = r * 256 + t;
        int pp  = lin >> 4;
        int c4  = lin & 15;
        float4 v = make_float4(0.f, 0.f, 0.f, 0.f);
        if (pp < n) {
            int pix = clist[pp];
            v = ((const float4*)d_xt)[(size_t)pix * 16 + c4];
        }
        xs4[pp * 16 + (c4 ^ ((pp >> 2) & 3))] = v;
    }
    __syncthreads();

    int og8 = (t & 7) << 3;     // 8 outputs = 4 f32x2 pairs
    int pg4 = (t >> 3) << 2;    // 4 pixels
    int key = (t >> 3) & 3;     // swizzle key for this pixel quad

    // acc init = bias (LDG from bt, L2-hot)
    unsigned long long acc[4][4];
    {
        const unsigned long long* bb =
            (const unsigned long long*)(bt + k * 64 + og8);
        unsigned long long b0 = bb[0], b1 = bb[1], b2 = bb[2], b3 = bb[3];
        #pragma unroll
        for (int pp = 0; pp < 4; pp++) {
            acc[pp][0] = b0; acc[pp][1] = b1; acc[pp][2] = b2; acc[pp][3] = b3;
        }
    }

    #pragma unroll 4
    for (int c4 = 0; c4 < 16; c4++) {
        unsigned long long w[4][4];
        #pragma unroll
        for (int kk = 0; kk < 4; kk++) {
            const ulonglong2* wrow = (const ulonglong2*)&Wsm[(c4 * 4 + kk) * 64 + og8];
            ulonglong2 wa = wrow[0];
            ulonglong2 wb = wrow[1];
            w[kk][0] = wa.x; w[kk][1] = wa.y; w[kk][2] = wb.x; w[kk][3] = wb.y;
        }
        int slot = c4 ^ key;
        #pragma unroll
        for (int pp = 0; pp < 4; pp++) {
            float4 xv = xs4[(pg4 + pp) * 16 + slot];
            unsigned long long x0 = bcast2(xv.x);
            unsigned long long x1 = bcast2(xv.y);
            unsigned long long x2 = bcast2(xv.z);
            unsigned long long x3 = bcast2(xv.w);
            #pragma unroll
            for (int op = 0; op < 4; op++) {
                unsigned long long a = acc[pp][op];
                a = ffma2(x0, w[0][op], a);
                a = ffma2(x1, w[1][op], a);
                a = ffma2(x2, w[2][op], a);
                a = ffma2(x3, w[3][op], a);
                acc[pp][op] = a;
            }
        }
    }

    __syncthreads();   // Wsm reads done; safe to alias as reduction buffer

    // write y + accumulate per-(batch,output) moments as f32x2
    unsigned long long s0[4] = {0,0,0,0}, q0[4] = {0,0,0,0};
    unsigned long long s1[4] = {0,0,0,0}, q1[4] = {0,0,0,0};
    #pragma unroll
    for (int pp = 0; pp < 4; pp++) {
        if (pg4 + pp < n) {
            int pix = clist[pg4 + pp];
            float2 y0 = unpk(acc[pp][0]);
            float2 y1 = unpk(acc[pp][1]);
            float2 y2 = unpk(acc[pp][2]);
            float2 y3 = unpk(acc[pp][3]);
            float4* dst = (float4*)&d_ysc[(size_t)pix * 64 + og8];
            dst[0] = make_float4(y0.x, y0.y, y1.x, y1.y);
            dst[1] = make_float4(y2.x, y2.y, y3.x, y3.y);
            if (pix < HW) {
                #pragma unroll
                for (int op = 0; op < 4; op++) {
                    s0[op] = addf2(s0[op], acc[pp][op]);
                    q0[op] = ffma2(acc[pp][op], acc[pp][op], q0[op]);
                }
            } else {
                #pragma unroll
                for (int op = 0; op < 4; op++) {
                    s1[op] = addf2(s1[op], acc[pp][op]);
                    q1[op] = ffma2(acc[pp][op], acc[pp][op], q1[op]);
                }
            }
        }
    }

    // lanes {og, og+8, og+16, og+24} share outputs -> xor-reduce 8 then 16
    #pragma unroll
    for (int op = 0; op < 4; op++) {
        s0[op] = addf2(s0[op], __shfl_xor_sync(0xffffffffu, s0[op], 8));
        q0[op] = addf2(q0[op], __shfl_xor_sync(0xffffffffu, q0[op], 8));
        s1[op] = addf2(s1[op], __shfl_xor_sync(0xffffffffu, s1[op], 8));
        q1[op] = addf2(q1[op], __shfl_xor_sync(0xffffffffu, q1[op], 8));
        s0[op] = addf2(s0[op], __shfl_xor_sync(0xffffffffu, s0[op], 16));
        q0[op] = addf2(q0[op], __shfl_xor_sync(0xffffffffu, q0[op], 16));
        s1[op] = addf2(s1[op], __shfl_xor_sync(0xffffffffu, s1[op], 16));
        q1[op] = addf2(q1[op], __shfl_xor_sync(0xffffffffu, q1[op], 16));
    }

    float* red = Wsm;                      // 8 warps x 256 floats = 8KB
    int w = t >> 5;
    if ((t & 31) < 8) {
        float* rr = &red[w * 256 + (t & 7) * 32];
        #pragma unroll
        for (int op = 0; op < 4; op++) {
            float2 v;
            v = unpk(s0[op]); rr[0  + 2*op] = v.x; rr[1  + 2*op] = v.y;
            v = unpk(q0[op]); rr[8  + 2*op] = v.x; rr[9  + 2*op] = v.y;
            v = unpk(s1[op]); rr[16 + 2*op] = v.x; rr[17 + 2*op] = v.y;
            v = unpk(q1[op]); rr[24 + 2*op] = v.x; rr[25 + 2*op] = v.y;
        }
    }
    __syncthreads();

    {
        int ss = t;                        // 256 sums, one per thread
        float v = 0.f;
        #pragma unroll
        for (int ww = 0; ww < 8; ww++) v += red[ww * 256 + ss];
        int ogl  = ss >> 5;
        int idx  = ss & 31;
        int o    = (ogl << 3) + (idx & 7);
        int isq  = (idx >> 3) & 1;
        int bsel = (idx >> 4) & 1;
        int chan = bsel * 64 + o;
        if (isq) atomicAdd(&d_sq[chan], v);
        else     atomicAdd(&d_sum[chan], v);
    }
}

// -------- kC: norm + leaky + transpose, vectorized (512 blk x 256 thr) ------
__device__ __forceinline__ int sw4(int p) { return (p ^ (p >> 2) ^ (p >> 4)) & 3; }

__global__ void __launch_bounds__(256)
kC(float* __restrict__ out) {
    __shared__ float tile[64 * 68];     // 17.4KB, stride-68 + xor-swizzled cols
    int t   = threadIdx.x;
    int p0  = blockIdx.x * 64;          // 64 pixels per block (single batch)
    int b   = p0 >> 14;
    int hw0 = p0 & (HW - 1);
    int c4  = t & 15;                   // channel quad
    int pr_ = t >> 4;                   // 0..15

    // per-thread norm constants for channels 4*c4..+3:  y = v*a + bb
    int chan = b * 64 + (c4 << 2);
    float4 s4 = *(const float4*)&d_sum[chan];
    float4 q4 = *(const float4*)&d_sq[chan];
    const float inv = 1.0f / 16384.0f;
    float m0 = s4.x * inv, m1 = s4.y * inv, m2 = s4.z * inv, m3 = s4.w * inv;
    float a0 = rsqrtf(q4.x * inv - m0 * m0 + 1e-5f);
    float a1 = rsqrtf(q4.y * inv - m1 * m1 + 1e-5f);
    float a2 = rsqrtf(q4.z * inv - m2 * m2 + 1e-5f);
    float a3 = rsqrtf(q4.w * inv - m3 * m3 + 1e-5f);
    float b0 = -m0 * a0, b1 = -m1 * a1, b2 = -m2 * a2, b3 = -m3 * a3;

    // phase 1: load pixel-major, normalize + leaky, store swizzled tile
    #pragma unroll
    for (int r = 0; r < 4; r++) {
        int pp = r * 16 + pr_;
        float4 v = *(const float4*)&d_ysc[(size_t)(p0 + pp) * 64 + (c4 << 2)];
        v.x = fmaf(v.x, a0, b0); v.x = fmaxf(v.x, 0.01f * v.x);
        v.y = fmaf(v.y, a1, b1); v.y = fmaxf(v.y, 0.01f * v.y);
        v.z = fmaf(v.z, a2, b2); v.z = fmaxf(v.z, 0.01f * v.z);
        v.w = fmaf(v.w, a3, b3); v.w = fmaxf(v.w, 0.01f * v.w);
        *(float4*)&tile[pp * 68 + ((c4 ^ sw4(pp)) << 2)] = v;
    }
    __syncthreads();

    // phase 2: read transposed (4 px per thread, fixed ch), float4 store
    #pragma unroll
    for (int r = 0; r < 4; r++) {
        int ch  = r * 16 + pr_;          // 0..63
        int pq  = c4;                    // px0 = 4*pq
        int chq = ch >> 2, chl = ch & 3;
        float4 v;
        int px = pq << 2;
        v.x = tile[(px + 0) * 68 + (((chq) ^ sw4(px + 0)) << 2) + chl];
        v.y = tile[(px + 1) * 68 + (((chq) ^ sw4(px + 1)) << 2) + chl];
        v.z = tile[(px + 2) * 68 + (((chq) ^ sw4(px + 2)) << 2) + chl];
        v.w = tile[(px + 3) * 68 + (((chq) ^ sw4(px + 3)) << 2) + chl];
        *(float4*)&out[(size_t)(b * 64 + ch) * HW + hw0 + px] = v;
    }

    // reset routing counters for the next graph replay (kC always runs last)
    if (blockIdx.x == 0 && t < NCLS) d_cnt[t] = 0;
}

extern "C" void kernel_launch(void* const* d_in, const int* in_sizes, int n_in,
                              void* d_out, int out_size) {
    const float* x      = (const float*)d_in[0];
    const float* layout = (const float*)d_in[1];
    const float* pr     = (const float*)d_in[2];
    const float* conv_w = (const float*)d_in[3];
    const float* conv_b = (const float*)d_in[4];
    const float* Wt     = (const float*)d_in[5];
    const float* bt     = (const float*)d_in[6];
    const float* pl     = (const float*)d_in[7];
    float* out = (float*)d_out;

    kA<<<RBLK + TBLK, 256>>>(x, layout, pr, conv_w, conv_b, pl);
    kB<<<291, 256>>>(Wt, bt);   // 291 >= max total (class,128-chunk) blocks
    kC<<<512, 256>>>(out);
}

// round 16
// speedup vs baseline: 1.0067x; 1.0067x over previous
#include <cuda_runtime.h>

#define HW   16384      // 128*128
#define NPIX 32768      // B * HW
#define NCLS 35

#define RBLK 128        // routing blocks (256 px each)
#define TBLK 256        // transpose blocks (128 px each)

// -------- device scratch (no allocs allowed) --------
__device__ int   d_cnt[NCLS];              // zero-init at load; re-zeroed by kC
__device__ int   d_clist[NCLS * NPIX];     // 4.6 MB
__device__ float d_xt[NPIX * 64];          // x' pixel-major, 8.4 MB
__device__ float d_ysc[NPIX * 64];         // y  pixel-major, 8.4 MB
__device__ float d_sum[128];
__device__ float d_sq[128];

// -------- packed f32x2 helpers (Blackwell FFMA2 — only via PTX) --------
__device__ __forceinline__ unsigned long long ffma2(unsigned long long a,
                                                    unsigned long long b,
                                                    unsigned long long c) {
    unsigned long long d;
    asm("fma.rn.f32x2 %0, %1, %2, %3;" : "=l"(d) : "l"(a), "l"(b), "l"(c));
    return d;
}
__device__ __forceinline__ unsigned long long addf2(unsigned long long a,
                                                    unsigned long long b) {
    unsigned long long d;
    asm("add.rn.f32x2 %0, %1, %2;" : "=l"(d) : "l"(a), "l"(b));
    return d;
}
__device__ __forceinline__ unsigned long long bcast2(float x) {
    unsigned long long d;
    unsigned xi = __float_as_uint(x);
    asm("mov.b64 %0, {%1, %1};" : "=l"(d) : "r"(xi));
    return d;
}
__device__ __forceinline__ float2 unpk(unsigned long long v) {
    float lo, hi;
    asm("mov.b64 {%0, %1}, %2;" : "=f"(lo), "=f"(hi) : "l"(v));
    return make_float2(lo, hi);
}

// -------- cp.async helpers (LDGSTS: fire-and-forget gmem->smem) -------------
__device__ __forceinline__ unsigned smem_u32(const void* p) {
    return (unsigned)__cvta_generic_to_shared(p);
}
__device__ __forceinline__ void cp16(unsigned dst, const void* src) {
    asm volatile("cp.async.cg.shared.global [%0], [%1], 16;"
                 :: "r"(dst), "l"(src));
}
__device__ __forceinline__ void cp16z(unsigned dst, const void* src, int sz) {
    asm volatile("cp.async.cg.shared.global [%0], [%1], 16, %2;"
                 :: "r"(dst), "l"(src), "r"(sz));
}
__device__ __forceinline__ void cp_wait_all() {
    asm volatile("cp.async.commit_group;\n\tcp.async.wait_group 0;" ::: "memory");
}

// 5-bit swizzle: all 16 values of ch-quad map to distinct slots
__device__ __forceinline__ int swz5(int ch) { return ((ch & 31) ^ (ch >> 2)) & 31; }

// -------- kA: role-split; all bulk loads via cp.async ------------------------
__global__ void __launch_bounds__(256, 4)
kA(const float* __restrict__ x, const float* __restrict__ layout,
   const float* __restrict__ pr, const float* __restrict__ conv_w,
   const float* __restrict__ conv_b, const float* __restrict__ pl) {
    __shared__ float shbuf[NCLS * 256];   // 35.8KB; routing stage / transpose stage
    int t   = threadIdx.x;
    int bid = blockIdx.x;
    unsigned shb = smem_u32(shbuf);

    if (bid < RBLK) {
        // ===== routing: 256 px/block; cp.async-staged argmax ================
        if (bid == 0 && t < 128) { d_sum[t] = 0.f; d_sq[t] = 0.f; }
        int p0  = bid * 256;
        int b   = p0 >> 14;
        int hw0 = p0 & (HW - 1);
        const float* lb = layout + (size_t)b * NCLS * HW + hw0;

        // 2240 async 16B chunks, zero register pressure, all in flight
        #pragma unroll
        for (int it = 0; it < 9; it++) {
            int idx = it * 256 + t;
            if (idx < NCLS * 64) {
                int row = idx >> 6;          // class
                int col = idx & 63;          // float4 within 256 px
                cp16(shb + (unsigned)(row * 256 + col * 4) * 4,
                     lb + (size_t)row * HW + col * 4);
            }
        }
        cp_wait_all();
        __syncthreads();

        // per-pixel argmax over 35 conflict-free LDS (first-max tie rule)
        float best = shbuf[t];
        int arg = 0;
        #pragma unroll
        for (int k = 1; k < NCLS; k++) {
            float v = shbuf[k * 256 + t];
            if (v > best) { best = v; arg = k; }
        }
        int slot = atomicAdd(&d_cnt[arg], 1);
        d_clist[arg * NPIX + slot] = p0 + t;
        return;
    }

    // ===== transpose: 128 px/block; cp.async ch-major stage + swizzle =======
    float* stage = shbuf;                // 64ch x 32 chunks x 4 = 8192 floats
    float* ssm   = shbuf + 8192;         // 128 floats
    int p0  = (bid - RBLK) * 128;
    int b   = p0 >> 14;
    int hw0 = p0 & (HW - 1);
    const float* xbase = x + (size_t)b * 64 * HW + hw0;

    // issue 8 async chunks/thread: chunk id -> (ch, pc); coalesced per warp
    #pragma unroll
    for (int r = 0; r < 8; r++) {
        int id = r * 256 + t;
        int ch = id >> 5;                 // 0..63
        int pc = id & 31;                 // 4-px chunk within channel
        int sl = pc ^ swz5(ch);
        cp16(shb + (unsigned)(ch * 128 + sl * 4) * 4,
             xbase + (size_t)ch * HW + pc * 4);
    }

    // pos-scalar s overlaps the async copies (independent small LDGs)
    if (t < 128) {
        int hw = hw0 + t;
        int i  = hw >> 7;
        int j  = hw & 127;
        int jm = j % 3, im = i % 3;
        float xc  = (jm == 0) ? 1.0f : -0.5f;
        float xsn = (jm == 0) ? 0.0f : ((jm == 1) ? 0.8660254f : -0.8660254f);
        float yc  = (im == 0) ? 1.0f : -0.5f;
        float ysn = (im == 0) ? 0.0f : ((im == 1) ? 0.8660254f : -0.8660254f);
        float px = (float)i * (2.0f / 128.0f) - 1.0f;
        float py = (float)j * (2.0f / 128.0f) - 1.0f;
        float pl0 = pl[hw], pl1 = pl[HW + hw];
        const float* prb = pr + b * 2 * HW;
        float pr0 = prb[hw], pr1 = prb[HW + hw];
        float s = px * conv_w[0] + py * conv_w[1] + pl0 * conv_w[2]
                + pl1 * conv_w[3] + pr0 * conv_w[4] + pr1 * conv_w[5]
                + xc * conv_w[6] + xsn * conv_w[7]
                + yc * conv_w[8] + ysn * conv_w[9] + conv_b[0];
        ssm[t] = s;
    }
    cp_wait_all();
    __syncthreads();

    // write pixel-major float4 rows from swizzled stage, fusing +s
    #pragma unroll
    for (int r = 0; r < 8; r++) {
        int lin = r * 256 + t;
        int pp  = lin >> 4;               // pixel 0..127
        int c4  = (lin & 15) << 2;        // channel quad base
        float s = ssm[pp];
        int pc  = pp >> 2, pw = pp & 3;
        float4 v;
        v.x = stage[(c4 + 0) * 128 + (pc ^ swz5(c4 + 0)) * 4 + pw] + s;
        v.y = stage[(c4 + 1) * 128 + (pc ^ swz5(c4 + 1)) * 4 + pw] + s;
        v.z = stage[(c4 + 2) * 128 + (pc ^ swz5(c4 + 2)) * 4 + pw] + s;
        v.w = stage[(c4 + 3) * 128 + (pc ^ swz5(c4 + 3)) * 4 + pw] + s;
        *(float4*)&d_xt[(size_t)(p0 + pp) * 64 + c4] = v;
    }
}

// -------- kB: grouped GEMM + in-block scan; cp.async prologue ---------------
__global__ void __launch_bounds__(256, 2)
kB(const float* __restrict__ Wt, const float* __restrict__ bt) {
    __shared__ float Wsm[64 * 64];     // 16KB; aliased as reduction buf after GEMM
    __shared__ float xs[128 * 64];     // 32KB; aliased as scan buf before gather

    int t   = threadIdx.x;
    int bid = blockIdx.x;

    // ---- per-block prefix scan of per-class 128-px chunk counts (warp 0) ----
    int* sc = (int*)xs;                // sc[35] inclusive prefix
    if (t < 32) {
        unsigned m = 0xffffffffu;
        int a = (t < NCLS) ? ((d_cnt[t] + 127) >> 7) : 0;
        int bch = (t < NCLS - 32) ? ((d_cnt[32 + t] + 127) >> 7) : 0;
        #pragma unroll
        for (int off = 1; off < 32; off <<= 1) {
            int u = __shfl_up_sync(m, a, off);
            if (t >= off) a += u;
        }
        #pragma unroll
        for (int off = 1; off < 4; off <<= 1) {
            int u = __shfl_up_sync(m, bch, off);
            if (t >= off) bch += u;
        }
        int totalA = __shfl_sync(m, a, 31);
        sc[t] = a;
        if (t < 3) sc[32 + t] = totalA + bch;
    }
    __syncthreads();

    int total = sc[NCLS - 1];
    if (bid >= total) return;          // uniform exit

    // smallest k with sc[k] > bid
    int lo = 0, hi = NCLS;
    #pragma unroll
    for (int it = 0; it < 6; it++) {
        int mid = (lo + hi) >> 1;
        if (mid < NCLS && sc[mid] <= bid) lo = mid + 1; else hi = mid;
    }
    int k      = lo;
    int pfx    = (k > 0) ? sc[k - 1] : 0;
    int base   = (bid - pfx) << 7;
    int n      = min(128, d_cnt[k] - base);
    const int* clist = d_clist + k * NPIX + base;
    __syncthreads();                   // everyone done reading sc before xs reuse

    unsigned wsm_u = smem_u32(Wsm);
    unsigned xs_u  = smem_u32(xs);

    // async: expert matrix (1024 chunks)
    const float4* Wk4 = (const float4*)(Wt + (size_t)k * 4096);
    #pragma unroll
    for (int r = 0; r < 4; r++)
        cp16(wsm_u + (unsigned)(r * 256 + t) * 16, Wk4 + r * 256 + t);

    // async: gather x' rows, xor-swizzled (zero-fill past n)
    #pragma unroll
    for (int r = 0; r < 8; r++) {
        int lin = r * 256 + t;
        int pp  = lin >> 4;
        int c4  = lin & 15;
        int pix = clist[min(pp, n - 1)];
        int sz  = (pp < n) ? 16 : 0;
        cp16z(xs_u + (unsigned)(pp * 16 + (c4 ^ ((pp >> 2) & 3))) * 16,
              (const float4*)d_xt + (size_t)pix * 16 + c4, sz);
    }
    cp_wait_all();
    __syncthreads();

    float4* xs4 = (float4*)xs;
    int og8 = (t & 7) << 3;     // 8 outputs = 4 f32x2 pairs
    int pg4 = (t >> 3) << 2;    // 4 pixels
    int key = (t >> 3) & 3;     // swizzle key for this pixel quad

    // acc init = bias (LDG from bt, L2-hot)
    unsigned long long acc[4][4];
    {
        const unsigned long long* bb =
            (const unsigned long long*)(bt + k * 64 + og8);
        unsigned long long b0 = bb[0], b1 = bb[1], b2 = bb[2], b3 = bb[3];
        #pragma unroll
        for (int pp = 0; pp < 4; pp++) {
            acc[pp][0] = b0; acc[pp][1] = b1; acc[pp][2] = b2; acc[pp][3] = b3;
        }
    }

    #pragma unroll 4
    for (int c4 = 0; c4 < 16; c4++) {
        unsigned long long w[4][4];
        #pragma unroll
        for (int kk = 0; kk < 4; kk++) {
            const ulonglong2* wrow = (const ulonglong2*)&Wsm[(c4 * 4 + kk) * 64 + og8];
            ulonglong2 wa = wrow[0];
            ulonglong2 wb = wrow[1];
            w[kk][0] = wa.x; w[kk][1] = wa.y; w[kk][2] = wb.x; w[kk][3] = wb.y;
        }
        int slot = c4 ^ key;
        #pragma unroll
        for (int pp = 0; pp < 4; pp++) {
            float4 xv = xs4[(pg4 + pp) * 16 + slot];
            unsigned long long x0 = bcast2(xv.x);
            unsigned long long x1 = bcast2(xv.y);
            unsigned long long x2 = bcast2(xv.z);
            unsigned long long x3 = bcast2(xv.w);
            #pragma unroll
            for (int op = 0; op < 4; op++) {
                unsigned long long a = acc[pp][op];
                a = ffma2(x0, w[0][op], a);
                a = ffma2(x1, w[1][op], a);
                a = ffma2(x2, w[2][op], a);
                a = ffma2(x3, w[3][op], a);
                acc[pp][op] = a;
            }
        }
    }

    __syncthreads();   // Wsm reads done; safe to alias as reduction buffer

    // write y + accumulate per-(batch,output) moments as f32x2
    unsigned long long s0[4] = {0,0,0,0}, q0[4] = {0,0,0,0};
    unsigned long long s1[4] = {0,0,0,0}, q1[4] = {0,0,0,0};
    #pragma unroll
    for (int pp = 0; pp < 4; pp++) {
        if (pg4 + pp < n) {
            int pix = clist[pg4 + pp];
            float2 y0 = unpk(acc[pp][0]);
            float2 y1 = unpk(acc[pp][1]);
            float2 y2 = unpk(acc[pp][2]);
            float2 y3 = unpk(acc[pp][3]);
            float4* dst = (float4*)&d_ysc[(size_t)pix * 64 + og8];
            dst[0] = make_float4(y0.x, y0.y, y1.x, y1.y);
            dst[1] = make_float4(y2.x, y2.y, y3.x, y3.y);
            if (pix < HW) {
                #pragma unroll
                for (int op = 0; op < 4; op++) {
                    s0[op] = addf2(s0[op], acc[pp][op]);
                    q0[op] = ffma2(acc[pp][op], acc[pp][op], q0[op]);
                }
            } else {
                #pragma unroll
                for (int op = 0; op < 4; op++) {
                    s1[op] = addf2(s1[op], acc[pp][op]);
                    q1[op] = ffma2(acc[pp][op], acc[pp][op], q1[op]);
                }
            }
        }
    }

    // lanes {og, og+8, og+16, og+24} share outputs -> xor-reduce 8 then 16
    #pragma unroll
    for (int op = 0; op < 4; op++) {
        s0[op] = addf2(s0[op], __shfl_xor_sync(0xffffffffu, s0[op], 8));
        q0[op] = addf2(q0[op], __shfl_xor_sync(0xffffffffu, q0[op], 8));
        s1[op] = addf2(s1[op], __shfl_xor_sync(0xffffffffu, s1[op], 8));
        q1[op] = addf2(q1[op], __shfl_xor_sync(0xffffffffu, q1[op], 8));
        s0[op] = addf2(s0[op], __shfl_xor_sync(0xffffffffu, s0[op], 16));
        q0[op] = addf2(q0[op], __shfl_xor_sync(0xffffffffu, q0[op], 16));
        s1[op] = addf2(s1[op], __shfl_xor_sync(0xffffffffu, s1[op], 16));
        q1[op] = addf2(q1[op], __shfl_xor_sync(0xffffffffu, q1[op], 16));
    }

    float* red = Wsm;                      // 8 warps x 256 floats = 8KB
    int w = t >> 5;
    if ((t & 31) < 8) {
        float* rr = &red[w * 256 + (t & 7) * 32];
        #pragma unroll
        for (int op = 0; op < 4; op++) {
            float2 v;
            v = unpk(s0[op]); rr[0  + 2*op] = v.x; rr[1  + 2*op] = v.y;
            v = unpk(q0[op]); rr[8  + 2*op] = v.x; rr[9  + 2*op] = v.y;
            v = unpk(s1[op]); rr[16 + 2*op] = v.x; rr[17 + 2*op] = v.y;
            v = unpk(q1[op]); rr[24 + 2*op] = v.x; rr[25 + 2*op] = v.y;
        }
    }
    __syncthreads();

    {
        int ss = t;                        // 256 sums, one per thread
        float v = 0.f;
        #pragma unroll
        for (int ww = 0; ww < 8; ww++) v += red[ww * 256 + ss];
        int ogl  = ss >> 5;
        int idx  = ss & 31;
        int o    = (ogl << 3) + (idx & 7);
        int isq  = (idx >> 3) & 1;
        int bsel = (idx >> 4) & 1;
        int chan = bsel * 64 + o;
        if (isq) atomicAdd(&d_sq[chan], v);
        else     atomicAdd(&d_sum[chan], v);
    }
}

// -------- kC: norm + leaky + transpose, vectorized (512 blk x 256 thr) ------
__device__ __forceinline__ int sw4(int p) { return (p ^ (p >> 2) ^ (p >> 4)) & 3; }

__global__ void __launch_bounds__(256)
kC(float* __restrict__ out) {
    __shared__ float tile[64 * 68];     // 17.4KB, stride-68 + xor-swizzled cols
    int t   = threadIdx.x;
    int p0  = blockIdx.x * 64;          // 64 pixels per block (single batch)
    int b   = p0 >> 14;
    int hw0 = p0 & (HW - 1);
    int c4  = t & 15;                   // channel quad
    int pr_ = t >> 4;                   // 0..15

    // per-thread norm constants for channels 4*c4..+3:  y = v*a + bb
    int chan = b * 64 + (c4 << 2);
    float4 s4 = *(const float4*)&d_sum[chan];
    float4 q4 = *(const float4*)&d_sq[chan];
    const float inv = 1.0f / 16384.0f;
    float m0 = s4.x * inv, m1 = s4.y * inv, m2 = s4.z * inv, m3 = s4.w * inv;
    float a0 = rsqrtf(q4.x * inv - m0 * m0 + 1e-5f);
    float a1 = rsqrtf(q4.y * inv - m1 * m1 + 1e-5f);
    float a2 = rsqrtf(q4.z * inv - m2 * m2 + 1e-5f);
    float a3 = rsqrtf(q4.w * inv - m3 * m3 + 1e-5f);
    float b0 = -m0 * a0, b1 = -m1 * a1, b2 = -m2 * a2, b3 = -m3 * a3;

    // phase 1: load pixel-major, normalize + leaky, store swizzled tile
    #pragma unroll
    for (int r = 0; r < 4; r++) {
        int pp = r * 16 + pr_;
        float4 v = *(const float4*)&d_ysc[(size_t)(p0 + pp) * 64 + (c4 << 2)];
        v.x = fmaf(v.x, a0, b0); v.x = fmaxf(v.x, 0.01f * v.x);
        v.y = fmaf(v.y, a1, b1); v.y = fmaxf(v.y, 0.01f * v.y);
        v.z = fmaf(v.z, a2, b2); v.z = fmaxf(v.z, 0.01f * v.z);
        v.w = fmaf(v.w, a3, b3); v.w = fmaxf(v.w, 0.01f * v.w);
        *(float4*)&tile[pp * 68 + ((c4 ^ sw4(pp)) << 2)] = v;
    }
    __syncthreads();

    // phase 2: read transposed (4 px per thread, fixed ch), float4 store
    #pragma unroll
    for (int r = 0; r < 4; r++) {
        int ch  = r * 16 + pr_;          // 0..63
        int pq  = c4;                    // px0 = 4*pq
        int chq = ch >> 2, chl = ch & 3;
        float4 v;
        int px = pq << 2;
        v.x = tile[(px + 0) * 68 + (((chq) ^ sw4(px + 0)) << 2) + chl];
        v.y = tile[(px + 1) * 68 + (((chq) ^ sw4(px + 1)) << 2) + chl];
        v.z = tile[(px + 2) * 68 + (((chq) ^ sw4(px + 2)) << 2) + chl];
        v.w = tile[(px + 3) * 68 + (((chq) ^ sw4(px + 3)) << 2) + chl];
        *(float4*)&out[(size_t)(b * 64 + ch) * HW + hw0 + px] = v;
    }

    // reset routing counters for the next graph replay (kC always runs last)
    if (blockIdx.x == 0 && t < NCLS) d_cnt[t] = 0;
}

extern "C" void kernel_launch(void* const* d_in, const int* in_sizes, int n_in,
                              void* d_out, int out_size) {
    const float* x      = (const float*)d_in[0];
    const float* layout = (const float*)d_in[1];
    const float* pr     = (const float*)d_in[2];
    const float* conv_w = (const float*)d_in[3];
    const float* conv_b = (const float*)d_in[4];
    const float* Wt     = (const float*)d_in[5];
    const float* bt     = (const float*)d_in[6];
    const float* pl     = (const float*)d_in[7];
    float* out = (float*)d_out;

    kA<<<RBLK + TBLK, 256>>>(x, layout, pr, conv_w, conv_b, pl);
    kB<<<291, 256>>>(Wt, bt);   // 291 >= max total (class,128-chunk) blocks
    kC<<<512, 256>>>(out);
}

// round 17
// speedup vs baseline: 1.2347x; 1.2264x over previous
#include <cuda_runtime.h>

#define HW   16384      // 128*128
#define NPIX 32768      // B * HW
#define NCLS 35

#define RBLK 128        // routing blocks (256 px each)
#define TBLK 256        // transpose blocks (128 px each)

// -------- device scratch (no allocs allowed) --------
__device__ int   d_cnt[NCLS];              // zero-init at load; re-zeroed by kC
__device__ int   d_clist[NCLS * NPIX];     // 4.6 MB
__device__ float d_xt[NPIX * 64];          // x' pixel-major, 8.4 MB
__device__ float d_ysc[NPIX * 64];         // y  pixel-major, 8.4 MB
__device__ float d_sum[128];
__device__ float d_sq[128];

// -------- packed f32x2 helpers (Blackwell FFMA2 — only via PTX) --------
__device__ __forceinline__ unsigned long long ffma2(unsigned long long a,
                                                    unsigned long long b,
                                                    unsigned long long c) {
    unsigned long long d;
    asm("fma.rn.f32x2 %0, %1, %2, %3;" : "=l"(d) : "l"(a), "l"(b), "l"(c));
    return d;
}
__device__ __forceinline__ unsigned long long addf2(unsigned long long a,
                                                    unsigned long long b) {
    unsigned long long d;
    asm("add.rn.f32x2 %0, %1, %2;" : "=l"(d) : "l"(a), "l"(b));
    return d;
}
__device__ __forceinline__ unsigned long long bcast2(float x) {
    unsigned long long d;
    unsigned xi = __float_as_uint(x);
    asm("mov.b64 %0, {%1, %1};" : "=l"(d) : "r"(xi));
    return d;
}
__device__ __forceinline__ float2 unpk(unsigned long long v) {
    float lo, hi;
    asm("mov.b64 {%0, %1}, %2;" : "=f"(lo), "=f"(hi) : "l"(v));
    return make_float2(lo, hi);
}

// -------- cp.async helpers (LDGSTS: fire-and-forget gmem->smem) -------------
__device__ __forceinline__ unsigned smem_u32(const void* p) {
    return (unsigned)__cvta_generic_to_shared(p);
}
__device__ __forceinline__ void cp16(unsigned dst, const void* src) {
    asm volatile("cp.async.cg.shared.global [%0], [%1], 16;"
                 :: "r"(dst), "l"(src));
}
__device__ __forceinline__ void cp16z(unsigned dst, const void* src, int sz) {
    asm volatile("cp.async.cg.shared.global [%0], [%1], 16, %2;"
                 :: "r"(dst), "l"(src), "r"(sz));
}
__device__ __forceinline__ void cp_wait_all() {
    asm volatile("cp.async.commit_group;\n\tcp.async.wait_group 0;" ::: "memory");
}

// 5-bit swizzle: all 16 values of ch-quad map to distinct slots
__device__ __forceinline__ int swz5(int ch) { return ((ch & 31) ^ (ch >> 2)) & 31; }

// -------- kA: role-split; hierarchical routing atomics ----------------------
__global__ void __launch_bounds__(256, 4)
kA(const float* __restrict__ x, const float* __restrict__ layout,
   const float* __restrict__ pr, const float* __restrict__ conv_w,
   const float* __restrict__ conv_b, const float* __restrict__ pl) {
    __shared__ float shbuf[NCLS * 256];   // 35.8KB; routing stage / transpose stage
    __shared__ int   scnt[NCLS];          // per-block class counts
    __shared__ int   sbase[NCLS];         // global base per class
    int t   = threadIdx.x;
    int bid = blockIdx.x;
    unsigned shb = smem_u32(shbuf);

    if (bid < RBLK) {
        // ===== routing: 256 px/block; smem-aggregated atomics ===============
        if (bid == 0 && t < 128) { d_sum[t] = 0.f; d_sq[t] = 0.f; }
        if (t < NCLS) scnt[t] = 0;
        int p0  = bid * 256;
        int b   = p0 >> 14;
        int hw0 = p0 & (HW - 1);
        const float* lb = layout + (size_t)b * NCLS * HW + hw0;

        // 2240 async 16B chunks, zero register pressure, all in flight
        #pragma unroll
        for (int it = 0; it < 9; it++) {
            int idx = it * 256 + t;
            if (idx < NCLS * 64) {
                int row = idx >> 6;          // class
                int col = idx & 63;          // float4 within 256 px
                cp16(shb + (unsigned)(row * 256 + col * 4) * 4,
                     lb + (size_t)row * HW + col * 4);
            }
        }
        cp_wait_all();
        __syncthreads();                    // layout staged + scnt zeroed

        // per-pixel argmax over 35 conflict-free LDS (first-max tie rule)
        float best = shbuf[t];
        int arg = 0;
        #pragma unroll
        for (int k = 1; k < NCLS; k++) {
            float v = shbuf[k * 256 + t];
            if (v > best) { best = v; arg = k; }
        }
        // level 1: block-local slot (smem atomic, per-SM resource)
        int lslot = atomicAdd(&scnt[arg], 1);
        __syncthreads();
        // level 2: ONE global atomic per (block, class) -> 35/block max
        if (t < NCLS) {
            int c = scnt[t];
            sbase[t] = (c > 0) ? atomicAdd(&d_cnt[t], c) : 0;
        }
        __syncthreads();
        d_clist[arg * NPIX + sbase[arg] + lslot] = p0 + t;
        return;
    }

    // ===== transpose: 128 px/block; cp.async ch-major stage + swizzle =======
    float* stage = shbuf;                // 64ch x 32 chunks x 4 = 8192 floats
    float* ssm   = shbuf + 8192;         // 128 floats
    int p0  = (bid - RBLK) * 128;
    int b   = p0 >> 14;
    int hw0 = p0 & (HW - 1);
    const float* xbase = x + (size_t)b * 64 * HW + hw0;

    // issue 8 async chunks/thread: chunk id -> (ch, pc); coalesced per warp
    #pragma unroll
    for (int r = 0; r < 8; r++) {
        int id = r * 256 + t;
        int ch = id >> 5;                 // 0..63
        int pc = id & 31;                 // 4-px chunk within channel
        int sl = pc ^ swz5(ch);
        cp16(shb + (unsigned)(ch * 128 + sl * 4) * 4,
             xbase + (size_t)ch * HW + pc * 4);
    }

    // pos-scalar s overlaps the async copies (independent small LDGs)
    if (t < 128) {
        int hw = hw0 + t;
        int i  = hw >> 7;
        int j  = hw & 127;
        int jm = j % 3, im = i % 3;
        float xc  = (jm == 0) ? 1.0f : -0.5f;
        float xsn = (jm == 0) ? 0.0f : ((jm == 1) ? 0.8660254f : -0.8660254f);
        float yc  = (im == 0) ? 1.0f : -0.5f;
        float ysn = (im == 0) ? 0.0f : ((im == 1) ? 0.8660254f : -0.8660254f);
        float px = (float)i * (2.0f / 128.0f) - 1.0f;
        float py = (float)j * (2.0f / 128.0f) - 1.0f;
        float pl0 = pl[hw], pl1 = pl[HW + hw];
        const float* prb = pr + b * 2 * HW;
        float pr0 = prb[hw], pr1 = prb[HW + hw];
        float s = px * conv_w[0] + py * conv_w[1] + pl0 * conv_w[2]
                + pl1 * conv_w[3] + pr0 * conv_w[4] + pr1 * conv_w[5]
                + xc * conv_w[6] + xsn * conv_w[7]
                + yc * conv_w[8] + ysn * conv_w[9] + conv_b[0];
        ssm[t] = s;
    }
    cp_wait_all();
    __syncthreads();

    // write pixel-major float4 rows from swizzled stage, fusing +s
    #pragma unroll
    for (int r = 0; r < 8; r++) {
        int lin = r * 256 + t;
        int pp  = lin >> 4;               // pixel 0..127
        int c4  = (lin & 15) << 2;        // channel quad base
        float s = ssm[pp];
        int pc  = pp >> 2, pw = pp & 3;
        float4 v;
        v.x = stage[(c4 + 0) * 128 + (pc ^ swz5(c4 + 0)) * 4 + pw] + s;
        v.y = stage[(c4 + 1) * 128 + (pc ^ swz5(c4 + 1)) * 4 + pw] + s;
        v.z = stage[(c4 + 2) * 128 + (pc ^ swz5(c4 + 2)) * 4 + pw] + s;
        v.w = stage[(c4 + 3) * 128 + (pc ^ swz5(c4 + 3)) * 4 + pw] + s;
        *(float4*)&d_xt[(size_t)(p0 + pp) * 64 + c4] = v;
    }
}

// -------- kB: grouped GEMM + in-block scan; cp.async prologue ---------------
__global__ void __launch_bounds__(256, 2)
kB(const float* __restrict__ Wt, const float* __restrict__ bt) {
    __shared__ float Wsm[64 * 64];     // 16KB; aliased as reduction buf after GEMM
    __shared__ float xs[128 * 64];     // 32KB; aliased as scan buf before gather

    int t   = threadIdx.x;
    int bid = blockIdx.x;

    // ---- per-block prefix scan of per-class 128-px chunk counts (warp 0) ----
    int* sc = (int*)xs;                // sc[35] inclusive prefix
    if (t < 32) {
        unsigned m = 0xffffffffu;
        int a = (t < NCLS) ? ((d_cnt[t] + 127) >> 7) : 0;
        int bch = (t < NCLS - 32) ? ((d_cnt[32 + t] + 127) >> 7) : 0;
        #pragma unroll
        for (int off = 1; off < 32; off <<= 1) {
            int u = __shfl_up_sync(m, a, off);
            if (t >= off) a += u;
        }
        #pragma unroll
        for (int off = 1; off < 4; off <<= 1) {
            int u = __shfl_up_sync(m, bch, off);
            if (t >= off) bch += u;
        }
        int totalA = __shfl_sync(m, a, 31);
        sc[t] = a;
        if (t < 3) sc[32 + t] = totalA + bch;
    }
    __syncthreads();

    int total = sc[NCLS - 1];
    if (bid >= total) return;          // uniform exit

    // smallest k with sc[k] > bid
    int lo = 0, hi = NCLS;
    #pragma unroll
    for (int it = 0; it < 6; it++) {
        int mid = (lo + hi) >> 1;
        if (mid < NCLS && sc[mid] <= bid) lo = mid + 1; else hi = mid;
    }
    int k      = lo;
    int pfx    = (k > 0) ? sc[k - 1] : 0;
    int base   = (bid - pfx) << 7;
    int n      = min(128, d_cnt[k] - base);
    const int* clist = d_clist + k * NPIX + base;
    __syncthreads();                   // everyone done reading sc before xs reuse

    unsigned wsm_u = smem_u32(Wsm);
    unsigned xs_u  = smem_u32(xs);

    // async: expert matrix (1024 chunks)
    const float4* Wk4 = (const float4*)(Wt + (size_t)k * 4096);
    #pragma unroll
    for (int r = 0; r < 4; r++)
        cp16(wsm_u + (unsigned)(r * 256 + t) * 16, Wk4 + r * 256 + t);

    // async: gather x' rows, xor-swizzled (zero-fill past n)
    #pragma unroll
    for (int r = 0; r < 8; r++) {
        int lin = r * 256 + t;
        int pp  = lin >> 4;
        int c4  = lin & 15;
        int pix = clist[min(pp, n - 1)];
        int sz  = (pp < n) ? 16 : 0;
        cp16z(xs_u + (unsigned)(pp * 16 + (c4 ^ ((pp >> 2) & 3))) * 16,
              (const float4*)d_xt + (size_t)pix * 16 + c4, sz);
    }
    cp_wait_all();
    __syncthreads();

    float4* xs4 = (float4*)xs;
    int og8 = (t & 7) << 3;     // 8 outputs = 4 f32x2 pairs
    int pg4 = (t >> 3) << 2;    // 4 pixels
    int key = (t >> 3) & 3;     // swizzle key for this pixel quad

    // acc init = bias (LDG from bt, L2-hot)
    unsigned long long acc[4][4];
    {
        const unsigned long long* bb =
            (const unsigned long long*)(bt + k * 64 + og8);
        unsigned long long b0 = bb[0], b1 = bb[1], b2 = bb[2], b3 = bb[3];
        #pragma unroll
        for (int pp = 0; pp < 4; pp++) {
            acc[pp][0] = b0; acc[pp][1] = b1; acc[pp][2] = b2; acc[pp][3] = b3;
        }
    }

    #pragma unroll 4
    for (int c4 = 0; c4 < 16; c4++) {
        unsigned long long w[4][4];
        #pragma unroll
        for (int kk = 0; kk < 4; kk++) {
            const ulonglong2* wrow = (const ulonglong2*)&Wsm[(c4 * 4 + kk) * 64 + og8];
            ulonglong2 wa = wrow[0];
            ulonglong2 wb = wrow[1];
            w[kk][0] = wa.x; w[kk][1] = wa.y; w[kk][2] = wb.x; w[kk][3] = wb.y;
        }
        int slot = c4 ^ key;
        #pragma unroll
        for (int pp = 0; pp < 4; pp++) {
            float4 xv = xs4[(pg4 + pp) * 16 + slot];
            unsigned long long x0 = bcast2(xv.x);
            unsigned long long x1 = bcast2(xv.y);
            unsigned long long x2 = bcast2(xv.z);
            unsigned long long x3 = bcast2(xv.w);
            #pragma unroll
            for (int op = 0; op < 4; op++) {
                unsigned long long a = acc[pp][op];
                a = ffma2(x0, w[0][op], a);
                a = ffma2(x1, w[1][op], a);
                a = ffma2(x2, w[2][op], a);
                a = ffma2(x3, w[3][op], a);
                acc[pp][op] = a;
            }
        }
    }

    __syncthreads();   // Wsm reads done; safe to alias as reduction buffer

    // write y + accumulate per-(batch,output) moments as f32x2
    unsigned long long s0[4] = {0,0,0,0}, q0[4] = {0,0,0,0};
    unsigned long long s1[4] = {0,0,0,0}, q1[4] = {0,0,0,0};
    #pragma unroll
    for (int pp = 0; pp < 4; pp++) {
        if (pg4 + pp < n) {
            int pix = clist[pg4 + pp];
            float2 y0 = unpk(acc[pp][0]);
            float2 y1 = unpk(acc[pp][1]);
            float2 y2 = unpk(acc[pp][2]);
            float2 y3 = unpk(acc[pp][3]);
            float4* dst = (float4*)&d_ysc[(size_t)pix * 64 + og8];
            dst[0] = make_float4(y0.x, y0.y, y1.x, y1.y);
            dst[1] = make_float4(y2.x, y2.y, y3.x, y3.y);
            if (pix < HW) {
                #pragma unroll
                for (int op = 0; op < 4; op++) {
                    s0[op] = addf2(s0[op], acc[pp][op]);
                    q0[op] = ffma2(acc[pp][op], acc[pp][op], q0[op]);
                }
            } else {
                #pragma unroll
                for (int op = 0; op < 4; op++) {
                    s1[op] = addf2(s1[op], acc[pp][op]);
                    q1[op] = ffma2(acc[pp][op], acc[pp][op], q1[op]);
                }
            }
        }
    }

    // lanes {og, og+8, og+16, og+24} share outputs -> xor-reduce 8 then 16
    #pragma unroll
    for (int op = 0; op < 4; op++) {
        s0[op] = addf2(s0[op], __shfl_xor_sync(0xffffffffu, s0[op], 8));
        q0[op] = addf2(q0[op], __shfl_xor_sync(0xffffffffu, q0[op], 8));
        s1[op] = addf2(s1[op], __shfl_xor_sync(0xffffffffu, s1[op], 8));
        q1[op] = addf2(q1[op], __shfl_xor_sync(0xffffffffu, q1[op], 8));
        s0[op] = addf2(s0[op], __shfl_xor_sync(0xffffffffu, s0[op], 16));
        q0[op] = addf2(q0[op], __shfl_xor_sync(0xffffffffu, q0[op], 16));
        s1[op] = addf2(s1[op], __shfl_xor_sync(0xffffffffu, s1[op], 16));
        q1[op] = addf2(q1[op], __shfl_xor_sync(0xffffffffu, q1[op], 16));
    }

    float* red = Wsm;                      // 8 warps x 256 floats = 8KB
    int w = t >> 5;
    if ((t & 31) < 8) {
        float* rr = &red[w * 256 + (t & 7) * 32];
        #pragma unroll
        for (int op = 0; op < 4; op++) {
            float2 v;
            v = unpk(s0[op]); rr[0  + 2*op] = v.x; rr[1  + 2*op] = v.y;
            v = unpk(q0[op]); rr[8  + 2*op] = v.x; rr[9  + 2*op] = v.y;
            v = unpk(s1[op]); rr[16 + 2*op] = v.x; rr[17 + 2*op] = v.y;
            v = unpk(q1[op]); rr[24 + 2*op] = v.x; rr[25 + 2*op] = v.y;
        }
    }
    __syncthreads();

    {
        int ss = t;                        // 256 sums, one per thread
        float v = 0.f;
        #pragma unroll
        for (int ww = 0; ww < 8; ww++) v += red[ww * 256 + ss];
        int ogl  = ss >> 5;
        int idx  = ss & 31;
        int o    = (ogl << 3) + (idx & 7);
        int isq  = (idx >> 3) & 1;
        int bsel = (idx >> 4) & 1;
        int chan = bsel * 64 + o;
        if (isq) atomicAdd(&d_sq[chan], v);
        else     atomicAdd(&d_sum[chan], v);
    }
}

// -------- kC: norm + leaky + transpose, vectorized (512 blk x 256 thr) ------
__device__ __forceinline__ int sw4(int p) { return (p ^ (p >> 2) ^ (p >> 4)) & 3; }

__global__ void __launch_bounds__(256)
kC(float* __restrict__ out) {
    __shared__ float tile[64 * 68];     // 17.4KB, stride-68 + xor-swizzled cols
    int t   = threadIdx.x;
    int p0  = blockIdx.x * 64;          // 64 pixels per block (single batch)
    int b   = p0 >> 14;
    int hw0 = p0 & (HW - 1);
    int c4  = t & 15;                   // channel quad
    int pr_ = t >> 4;                   // 0..15

    // per-thread norm constants for channels 4*c4..+3:  y = v*a + bb
    int chan = b * 64 + (c4 << 2);
    float4 s4 = *(const float4*)&d_sum[chan];
    float4 q4 = *(const float4*)&d_sq[chan];
    const float inv = 1.0f / 16384.0f;
    float m0 = s4.x * inv, m1 = s4.y * inv, m2 = s4.z * inv, m3 = s4.w * inv;
    float a0 = rsqrtf(q4.x * inv - m0 * m0 + 1e-5f);
    float a1 = rsqrtf(q4.y * inv - m1 * m1 + 1e-5f);
    float a2 = rsqrtf(q4.z * inv - m2 * m2 + 1e-5f);
    float a3 = rsqrtf(q4.w * inv - m3 * m3 + 1e-5f);
    float b0 = -m0 * a0, b1 = -m1 * a1, b2 = -m2 * a2, b3 = -m3 * a3;

    // phase 1: load pixel-major, normalize + leaky, store swizzled tile
    #pragma unroll
    for (int r = 0; r < 4; r++) {
        int pp = r * 16 + pr_;
        float4 v = *(const float4*)&d_ysc[(size_t)(p0 + pp) * 64 + (c4 << 2)];
        v.x = fmaf(v.x, a0, b0); v.x = fmaxf(v.x, 0.01f * v.x);
        v.y = fmaf(v.y, a1, b1); v.y = fmaxf(v.y, 0.01f * v.y);
        v.z = fmaf(v.z, a2, b2); v.z = fmaxf(v.z, 0.01f * v.z);
        v.w = fmaf(v.w, a3, b3); v.w = fmaxf(v.w, 0.01f * v.w);
        *(float4*)&tile[pp * 68 + ((c4 ^ sw4(pp)) << 2)] = v;
    }
    __syncthreads();

    // phase 2: read transposed (4 px per thread, fixed ch), float4 store
    #pragma unroll
    for (int r = 0; r < 4; r++) {
        int ch  = r * 16 + pr_;          // 0..63
        int pq  = c4;                    // px0 = 4*pq
        int chq = ch >> 2, chl = ch & 3;
        float4 v;
        int px = pq << 2;
        v.x = tile[(px + 0) * 68 + (((chq) ^ sw4(px + 0)) << 2) + chl];
        v.y = tile[(px + 1) * 68 + (((chq) ^ sw4(px + 1)) << 2) + chl];
        v.z = tile[(px + 2) * 68 + (((chq) ^ sw4(px + 2)) << 2) + chl];
        v.w = tile[(px + 3) * 68 + (((chq) ^ sw4(px + 3)) << 2) + chl];
        *(float4*)&out[(size_t)(b * 64 + ch) * HW + hw0 + px] = v;
    }

    // reset routing counters for the next graph replay (kC always runs last)
    if (blockIdx.x == 0 && t < NCLS) d_cnt[t] = 0;
}

extern "C" void kernel_launch(void* const* d_in, const int* in_sizes, int n_in,
                              void* d_out, int out_size) {
    const float* x      = (const float*)d_in[0];
    const float* layout = (const float*)d_in[1];
    const float* pr     = (const float*)d_in[2];
    const float* conv_w = (const float*)d_in[3];
    const float* conv_b = (const float*)d_in[4];
    const float* Wt     = (const float*)d_in[5];
    const float* bt     = (const float*)d_in[6];
    const float* pl     = (const float*)d_in[7];
    float* out = (float*)d_out;

    kA<<<RBLK + TBLK, 256>>>(x, layout, pr, conv_w, conv_b, pl);
    kB<<<291, 256>>>(Wt, bt);   // 291 >= max total (class,128-chunk) blocks
    kC<<<512, 256>>>(out);
}